// round 4
// baseline (speedup 1.0000x reference)
#include <cuda_runtime.h>
#include <cstddef>
#include <cstdint>

// GRU_13907104105002: bidirectional GRU (T=200,B=4096,I=3,H=32) + FC(C=1).
// R4 = R3 with the unsupported redux.sync.add.f32 replaced by a fused dual-tree
// shuffle reduction (6 SHFLs reduce BOTH batch streams' FC dots).
// 2 batch elements per warp (ILP-2); warp = (dir, batch-pair), lane = hidden
// index. Lane i keeps h_i for both streams + W_hh gate rows {i,32+i,64+i} as
// f32x2 pairs along j (96 regs, shared by both streams). h broadcast via
// per-warp SMEM (2 STS + 16 LDS.128 per step, zero syncs). Sigmoids via
// tanh.approx; candidate tanh exact (__expf). fwd writes out, bwd writes
// scratch, float4 combine kernel adds.

#define TT 200
#define BN 4096
#define HH 32

using ull = unsigned long long;

__device__ float g_scr[TT * BN];  // 3.3 MB scratch for backward dots

__device__ __forceinline__ ull pack2(float a, float b) {
    ull r; asm("mov.b64 %0, {%1, %2};" : "=l"(r) : "f"(a), "f"(b)); return r;
}
__device__ __forceinline__ ull fma2(ull a, ull b, ull c) {
    ull d; asm("fma.rn.f32x2 %0, %1, %2, %3;" : "=l"(d) : "l"(a), "l"(b), "l"(c)); return d;
}
__device__ __forceinline__ ull add2(ull a, ull b) {
    ull d; asm("add.rn.f32x2 %0, %1, %2;" : "=l"(d) : "l"(a), "l"(b)); return d;
}
__device__ __forceinline__ float hsum2(ull a) {
    float lo, hi; asm("mov.b64 {%0, %1}, %2;" : "=f"(lo), "=f"(hi) : "l"(a)); return lo + hi;
}
__device__ __forceinline__ float tanh_fast(float x) {           // HW approx, rel err ~5e-4
    float y; asm("tanh.approx.f32 %0, %1;" : "=f"(y) : "f"(x)); return y;
}
__device__ __forceinline__ float sigm(float x) {                // via tanh.approx
    return fmaf(tanh_fast(0.5f * x), 0.5f, 0.5f);
}
__device__ __forceinline__ float tanh_exact(float x) {          // for candidate gate n
    float e = __expf(2.f * x);
    return 1.f - __fdividef(2.f, e + 1.f);
}

__global__ __launch_bounds__(128, 3)
void gru_both(const float* __restrict__ x,
              const float* __restrict__ w_ih_f, const float* __restrict__ w_hh_f,
              const float* __restrict__ b_ih_f, const float* __restrict__ b_hh_f,
              const float* __restrict__ w_ih_b, const float* __restrict__ w_hh_b,
              const float* __restrict__ b_ih_b, const float* __restrict__ b_hh_b,
              const float* __restrict__ fc_w, const float* __restrict__ fc_b,
              float* __restrict__ out)
{
    __shared__ __align__(16) float hbuf[4][2][HH];   // [warp][batch-stream][hidden]

    const int lane = threadIdx.x & 31;
    const int w    = threadIdx.x >> 5;
    const int gw   = blockIdx.x * 4 + w;        // 0..4095 warps
    const int dir  = gw >> 11;                  // 2048 warps per direction
    const int bp   = gw & 2047;                 // batch pair index
    const int b0   = bp * 2;                    // even -> float2-aligned x

    const float* w_ih = dir ? w_ih_b : w_ih_f;
    const float* w_hh = dir ? w_hh_b : w_hh_f;
    const float* b_ih = dir ? b_ih_b : b_ih_f;
    const float* b_hh = dir ? b_hh_b : b_hh_f;

    uint32_t sbase;
    asm("{ .reg .u64 t; cvta.to.shared.u64 t, %1; cvt.u32.u64 %0, t; }"
        : "=r"(sbase) : "l"((const void*)hbuf));
    const uint32_t r0b = sbase + (uint32_t)w * 256u;        // stream-0 region
    const uint32_t r1b = r0b + 128u;                        // stream-1 region
    const uint32_t st0 = r0b + (lane << 2);
    const uint32_t st1 = r1b + (lane << 2);

    // W_hh rows for this lane's three gates, packed pairs along j (row = 128B)
    const ull* pr = reinterpret_cast<const ull*>(w_hh + (size_t)lane * HH);
    const ull* pz = reinterpret_cast<const ull*>(w_hh + (size_t)(HH + lane) * HH);
    const ull* pn = reinterpret_cast<const ull*>(w_hh + (size_t)(2 * HH + lane) * HH);
    ull wr[16], wz[16], wn[16];
#pragma unroll
    for (int k = 0; k < 16; k++) { wr[k] = pr[k]; wz[k] = pz[k]; wn[k] = pn[k]; }

    const float wxr0 = w_ih[lane * 3 + 0], wxr1 = w_ih[lane * 3 + 1], wxr2 = w_ih[lane * 3 + 2];
    const float wxz0 = w_ih[(HH + lane) * 3 + 0], wxz1 = w_ih[(HH + lane) * 3 + 1], wxz2 = w_ih[(HH + lane) * 3 + 2];
    const float wxn0 = w_ih[(2 * HH + lane) * 3 + 0], wxn1 = w_ih[(2 * HH + lane) * 3 + 1], wxn2 = w_ih[(2 * HH + lane) * 3 + 2];

    const float br  = b_ih[lane] + b_hh[lane];
    const float bz  = b_ih[HH + lane] + b_hh[HH + lane];
    const float bxn = b_ih[2 * HH + lane];
    const float bhn = b_hh[2 * HH + lane];
    const float fcw = fc_w[dir * HH + lane];
    const float fcb = fc_b[0];

    float h0 = 0.f, h1 = 0.f;
    asm volatile("st.shared.f32 [%0], %1;" :: "r"(st0), "f"(h0));
    asm volatile("st.shared.f32 [%0], %1;" :: "r"(st1), "f"(h1));

    // Prefetch x for first step: 6 floats for both batches via 3x float2
    const int tfirst = dir ? (TT - 1) : 0;
    const float2* xq0 = reinterpret_cast<const float2*>(x + ((size_t)tfirst * BN + b0) * 3);
    float2 e0 = xq0[0], e1 = xq0[1], e2 = xq0[2];

    for (int s = 0; s < TT; s++) {
        const int t  = dir ? (TT - 1 - s) : s;
        const int tn = dir ? (t > 0 ? t - 1 : 0) : (t < TT - 1 ? t + 1 : TT - 1);
        const float2* xq = reinterpret_cast<const float2*>(x + ((size_t)tn * BN + b0) * 3);
        const float2 f0 = xq[0], f1 = xq[1], f2 = xq[2];      // prefetch next step

        // unpack current x: b0 = (e0.x,e0.y,e1.x), b1 = (e1.y,e2.x,e2.y)
        const float xa0 = e0.x, xa1 = e0.y, xa2 = e1.x;
        const float xb0 = e1.y, xb1 = e2.x, xb2 = e2.y;

        // input-gate preactivations folded into accumulator inits
        const float xra = fmaf(wxr2, xa2, fmaf(wxr1, xa1, fmaf(wxr0, xa0, br)));
        const float xza = fmaf(wxz2, xa2, fmaf(wxz1, xa1, fmaf(wxz0, xa0, bz)));
        const float xna = fmaf(wxn2, xa2, fmaf(wxn1, xa1, fmaf(wxn0, xa0, bxn)));
        const float xrb = fmaf(wxr2, xb2, fmaf(wxr1, xb1, fmaf(wxr0, xb0, br)));
        const float xzb = fmaf(wxz2, xb2, fmaf(wxz1, xb1, fmaf(wxz0, xb0, bz)));
        const float xnb = fmaf(wxn2, xb2, fmaf(wxn1, xb1, fmaf(wxn0, xb0, bxn)));

        ull arA = pack2(xra, 0.f), azA = pack2(xza, 0.f), anA = pack2(bhn, 0.f);
        ull arA1 = 0, azA1 = 0, anA1 = 0;
        ull arB = pack2(xrb, 0.f), azB = pack2(xzb, 0.f), anB = pack2(bhn, 0.f);
        ull arB1 = 0, azB1 = 0, anB1 = 0;

#pragma unroll
        for (int q = 0; q < 8; q++) {
            float a0, a1, a2, a3, c0, c1, c2, c3;
            asm volatile("ld.shared.v4.f32 {%0,%1,%2,%3}, [%4];"
                         : "=f"(a0), "=f"(a1), "=f"(a2), "=f"(a3) : "r"(r0b + q * 16));
            asm volatile("ld.shared.v4.f32 {%0,%1,%2,%3}, [%4];"
                         : "=f"(c0), "=f"(c1), "=f"(c2), "=f"(c3) : "r"(r1b + q * 16));
            const ull pa0 = pack2(a0, a1), pa1 = pack2(a2, a3);
            const ull pb0 = pack2(c0, c1), pb1 = pack2(c2, c3);
            const ull w0r = wr[2 * q], w1r = wr[2 * q + 1];
            const ull w0z = wz[2 * q], w1z = wz[2 * q + 1];
            const ull w0n = wn[2 * q], w1n = wn[2 * q + 1];
            arA = fma2(w0r, pa0, arA);   arA1 = fma2(w1r, pa1, arA1);
            arB = fma2(w0r, pb0, arB);   arB1 = fma2(w1r, pb1, arB1);
            azA = fma2(w0z, pa0, azA);   azA1 = fma2(w1z, pa1, azA1);
            azB = fma2(w0z, pb0, azB);   azB1 = fma2(w1z, pb1, azB1);
            anA = fma2(w0n, pa0, anA);   anA1 = fma2(w1n, pa1, anA1);
            anB = fma2(w0n, pb0, anB);   anB1 = fma2(w1n, pb1, anB1);
        }

        // batch stream A
        {
            const float pre_r = hsum2(add2(arA, arA1));
            const float pre_z = hsum2(add2(azA, azA1));
            const float hn    = hsum2(add2(anA, anA1));
            const float r = sigm(pre_r);
            const float z = sigm(pre_z);
            const float n = tanh_exact(fmaf(r, hn, xna));
            h0 = fmaf(z, h0 - n, n);
        }
        // batch stream B
        {
            const float pre_r = hsum2(add2(arB, arB1));
            const float pre_z = hsum2(add2(azB, azB1));
            const float hn    = hsum2(add2(anB, anB1));
            const float r = sigm(pre_r);
            const float z = sigm(pre_z);
            const float n = tanh_exact(fmaf(r, hn, xnb));
            h1 = fmaf(z, h1 - n, n);
        }

        asm volatile("st.shared.f32 [%0], %1;" :: "r"(st0), "f"(h0));
        asm volatile("st.shared.f32 [%0], %1;" :: "r"(st1), "f"(h1));

        // FC (C=1): fused dual-tree reduction — 6 SHFLs reduce BOTH streams.
        // Cross-half fold: lanes <16 accumulate stream A, lanes >=16 stream B;
        // then 4 xor-shuffles within halves. s0 lands in lane 0, s1 in lane 16.
        {
            const float v0 = h0 * fcw;
            const float v1 = h1 * fcw;
            const float o0 = __shfl_xor_sync(0xffffffffu, v0, 16);
            const float o1 = __shfl_xor_sync(0xffffffffu, v1, 16);
            float c = (lane < 16) ? (v0 + o0) : (v1 + o1);
#pragma unroll
            for (int m = 8; m >= 1; m >>= 1) c += __shfl_xor_sync(0xffffffffu, c, m);
            if ((lane & 15) == 0) {
                const size_t oi = (size_t)t * BN + b0 + (lane >> 4);
                if (dir == 0) out[oi] = c + fcb;
                else          g_scr[oi] = c;
            }
        }

        e0 = f0; e1 = f1; e2 = f2;
    }
}

__global__ __launch_bounds__(256)
void combine_add(float* __restrict__ out)
{
    const int i = blockIdx.x * blockDim.x + threadIdx.x;   // 204800 float4s
    float4* o = reinterpret_cast<float4*>(out);
    const float4* s = reinterpret_cast<const float4*>(g_scr);
    float4 a = o[i];
    const float4 c = s[i];
    a.x += c.x; a.y += c.y; a.z += c.z; a.w += c.w;
    o[i] = a;
}

extern "C" void kernel_launch(void* const* d_in, const int* in_sizes, int n_in,
                              void* d_out, int out_size)
{
    (void)in_sizes; (void)n_in; (void)out_size;
    const float* x      = (const float*)d_in[0];
    const float* w_ih_f = (const float*)d_in[1];
    const float* w_hh_f = (const float*)d_in[2];
    const float* b_ih_f = (const float*)d_in[3];
    const float* b_hh_f = (const float*)d_in[4];
    const float* w_ih_b = (const float*)d_in[5];
    const float* w_hh_b = (const float*)d_in[6];
    const float* b_ih_b = (const float*)d_in[7];
    const float* b_hh_b = (const float*)d_in[8];
    const float* fc_w   = (const float*)d_in[9];
    const float* fc_b   = (const float*)d_in[10];
    float* out = (float*)d_out;

    gru_both<<<1024, 128>>>(x, w_ih_f, w_hh_f, b_ih_f, b_hh_f,
                            w_ih_b, w_hh_b, b_ih_b, b_hh_b, fc_w, fc_b, out);
    combine_add<<<(TT * BN / 4) / 256, 256>>>(out);
}

// round 5
// speedup vs baseline: 1.2874x; 1.2874x over previous
#include <cuda_runtime.h>
#include <cstddef>
#include <cstdint>

// GRU_13907104105002: bidirectional GRU (T=200,B=4096,I=3,H=32) + FC(C=1).
// R5: R1's shfl-broadcast inner loop (measured 0.71x faster per step than smem
// broadcast) + R2's structure (one kernel, both directions, no RMW).
// warp = (dir, batch), lane = hidden index. Lane i keeps h_i + W_hh gate rows
// {i,32+i,64+i} as f32x2 pairs along j (96 regs). h broadcast via 32 shfl/step,
// dual fma2 chains per gate. ALL activations via tanh.approx.f32 (R4 measured
// approx-sigmoid cost: rel_err 3.6e-7 -> 6.0e-7; preactivations are small so
// the approx is near-exact). fwd writes out, bwd writes __device__ scratch,
// float4 combine kernel adds.

#define TT 200
#define BN 4096
#define HH 32

using ull = unsigned long long;

__device__ float g_scr[TT * BN];  // 3.3 MB scratch for backward dots

__device__ __forceinline__ ull pack2(float a, float b) {
    ull r; asm("mov.b64 %0, {%1, %2};" : "=l"(r) : "f"(a), "f"(b)); return r;
}
__device__ __forceinline__ ull fma2(ull a, ull b, ull c) {
    ull d; asm("fma.rn.f32x2 %0, %1, %2, %3;" : "=l"(d) : "l"(a), "l"(b), "l"(c)); return d;
}
__device__ __forceinline__ ull add2(ull a, ull b) {
    ull d; asm("add.rn.f32x2 %0, %1, %2;" : "=l"(d) : "l"(a), "l"(b)); return d;
}
__device__ __forceinline__ float hsum2(ull a) {
    float lo, hi; asm("mov.b64 {%0, %1}, %2;" : "=f"(lo), "=f"(hi) : "l"(a)); return lo + hi;
}
__device__ __forceinline__ float tanh_fast(float x) {
    float y; asm("tanh.approx.f32 %0, %1;" : "=f"(y) : "f"(x)); return y;
}
__device__ __forceinline__ float sigm(float x) {
    return fmaf(tanh_fast(0.5f * x), 0.5f, 0.5f);
}

__global__ __launch_bounds__(128, 3)
void gru_both(const float* __restrict__ x,
              const float* __restrict__ w_ih_f, const float* __restrict__ w_hh_f,
              const float* __restrict__ b_ih_f, const float* __restrict__ b_hh_f,
              const float* __restrict__ w_ih_b, const float* __restrict__ w_hh_b,
              const float* __restrict__ b_ih_b, const float* __restrict__ b_hh_b,
              const float* __restrict__ fc_w, const float* __restrict__ fc_b,
              float* __restrict__ out)
{
    const int lane = threadIdx.x & 31;
    const int gw   = blockIdx.x * 4 + (threadIdx.x >> 5);   // 0..8191
    const int dir  = gw >> 12;                               // 0 fwd, 1 bwd
    const int b    = gw & (BN - 1);

    const float* w_ih = dir ? w_ih_b : w_ih_f;
    const float* w_hh = dir ? w_hh_b : w_hh_f;
    const float* b_ih = dir ? b_ih_b : b_ih_f;
    const float* b_hh = dir ? b_hh_b : b_hh_f;

    // W_hh rows for this lane's three gates, packed pairs along j (row = 128B)
    const ull* pr = reinterpret_cast<const ull*>(w_hh + (size_t)lane * HH);
    const ull* pz = reinterpret_cast<const ull*>(w_hh + (size_t)(HH + lane) * HH);
    const ull* pn = reinterpret_cast<const ull*>(w_hh + (size_t)(2 * HH + lane) * HH);
    ull wr[16], wz[16], wn[16];
#pragma unroll
    for (int k = 0; k < 16; k++) { wr[k] = pr[k]; wz[k] = pz[k]; wn[k] = pn[k]; }

    const float wxr0 = w_ih[lane * 3 + 0], wxr1 = w_ih[lane * 3 + 1], wxr2 = w_ih[lane * 3 + 2];
    const float wxz0 = w_ih[(HH + lane) * 3 + 0], wxz1 = w_ih[(HH + lane) * 3 + 1], wxz2 = w_ih[(HH + lane) * 3 + 2];
    const float wxn0 = w_ih[(2 * HH + lane) * 3 + 0], wxn1 = w_ih[(2 * HH + lane) * 3 + 1], wxn2 = w_ih[(2 * HH + lane) * 3 + 2];

    const float br  = b_ih[lane] + b_hh[lane];
    const float bz  = b_ih[HH + lane] + b_hh[HH + lane];
    const float bxn = b_ih[2 * HH + lane];
    const float bhn = b_hh[2 * HH + lane];
    const float fcw = fc_w[dir * HH + lane];
    const float fcb = fc_b[0];

    float h = 0.f;

    // Prefetch x for first step
    const int t0 = dir ? (TT - 1) : 0;
    const float* xp = x + ((size_t)t0 * BN + b) * 3;
    float x0 = xp[0], x1 = xp[1], x2 = xp[2];

    for (int s = 0; s < TT; s++) {
        const int t  = dir ? (TT - 1 - s) : s;
        const int tn = dir ? (t > 0 ? t - 1 : 0) : (t < TT - 1 ? t + 1 : TT - 1);
        const float* xq = x + ((size_t)tn * BN + b) * 3;
        const float nx0 = xq[0], nx1 = xq[1], nx2 = xq[2];   // prefetch next step

        // input-gate preactivations; biases folded into accumulator inits
        const float xr = fmaf(wxr2, x2, fmaf(wxr1, x1, fmaf(wxr0, x0, br)));
        const float xz = fmaf(wxz2, x2, fmaf(wxz1, x1, fmaf(wxz0, x0, bz)));
        const float xn = fmaf(wxn2, x2, fmaf(wxn1, x1, fmaf(wxn0, x0, bxn)));

        // hg = W_hh @ h via shfl broadcast; dual chains per gate
        ull ar0 = pack2(xr, 0.f), az0 = pack2(xz, 0.f), an0 = pack2(bhn, 0.f);
        ull ar1 = 0, az1 = 0, an1 = 0;
#pragma unroll
        for (int k = 0; k < 8; k++) {
            const float a0 = __shfl_sync(0xffffffffu, h, 4 * k + 0);
            const float a1 = __shfl_sync(0xffffffffu, h, 4 * k + 1);
            const float a2 = __shfl_sync(0xffffffffu, h, 4 * k + 2);
            const float a3 = __shfl_sync(0xffffffffu, h, 4 * k + 3);
            const ull p0 = pack2(a0, a1);
            const ull p1 = pack2(a2, a3);
            ar0 = fma2(wr[2 * k], p0, ar0);   ar1 = fma2(wr[2 * k + 1], p1, ar1);
            az0 = fma2(wz[2 * k], p0, az0);   az1 = fma2(wz[2 * k + 1], p1, az1);
            an0 = fma2(wn[2 * k], p0, an0);   an1 = fma2(wn[2 * k + 1], p1, an1);
        }

        const float pre_r = hsum2(add2(ar0, ar1));
        const float pre_z = hsum2(add2(az0, az1));
        const float hn    = hsum2(add2(an0, an1));

        const float r = sigm(pre_r);
        const float z = sigm(pre_z);
        const float n = tanh_fast(fmaf(r, hn, xn));
        h = fmaf(z, h - n, n);   // (1-z)*n + z*h

        // FC (C=1): 5-shfl butterfly, off the recurrence critical path
        float v = h * fcw;
#pragma unroll
        for (int m = 16; m >= 1; m >>= 1) v += __shfl_xor_sync(0xffffffffu, v, m);
        if (lane == 0) {
            const size_t oi = (size_t)t * BN + b;
            if (dir == 0) out[oi] = v + fcb;
            else          g_scr[oi] = v;
        }

        x0 = nx0; x1 = nx1; x2 = nx2;
    }
}

__global__ __launch_bounds__(256)
void combine_add(float* __restrict__ out)
{
    const int i = blockIdx.x * blockDim.x + threadIdx.x;   // 204800 float4s
    float4* o = reinterpret_cast<float4*>(out);
    const float4* s = reinterpret_cast<const float4*>(g_scr);
    float4 a = o[i];
    const float4 c = s[i];
    a.x += c.x; a.y += c.y; a.z += c.z; a.w += c.w;
    o[i] = a;
}

extern "C" void kernel_launch(void* const* d_in, const int* in_sizes, int n_in,
                              void* d_out, int out_size)
{
    (void)in_sizes; (void)n_in; (void)out_size;
    const float* x      = (const float*)d_in[0];
    const float* w_ih_f = (const float*)d_in[1];
    const float* w_hh_f = (const float*)d_in[2];
    const float* b_ih_f = (const float*)d_in[3];
    const float* b_hh_f = (const float*)d_in[4];
    const float* w_ih_b = (const float*)d_in[5];
    const float* w_hh_b = (const float*)d_in[6];
    const float* b_ih_b = (const float*)d_in[7];
    const float* b_hh_b = (const float*)d_in[8];
    const float* fc_w   = (const float*)d_in[9];
    const float* fc_b   = (const float*)d_in[10];
    float* out = (float*)d_out;

    gru_both<<<2048, 128>>>(x, w_ih_f, w_hh_f, b_ih_f, b_hh_f,
                            w_ih_b, w_hh_b, b_ih_b, b_hh_b, fc_w, fc_b, out);
    combine_add<<<(TT * BN / 4) / 256, 256>>>(out);
}

// round 6
// speedup vs baseline: 1.4280x; 1.1092x over previous
#include <cuda_runtime.h>
#include <cstddef>
#include <cstdint>

// GRU_13907104105002: bidirectional GRU (T=200,B=4096,I=3,H=32) + FC(C=1).
// R6: MIO-bound model (74 MIO-cyc/batch-step measured). Replace the 32-shfl
// h-broadcast with 1 STS.32 + 16 LDS.64 broadcast loads (8B/lane/instr vs
// 4B for shfl, and the ull pair feeds fma2 directly -> 16 pack2 removed).
// warp = (dir, batch), lane = hidden index; W_hh gate rows {i,32+i,64+i} in
// registers as f32x2 pairs (96 regs). All activations tanh.approx. fwd writes
// out, bwd writes __device__ scratch, float4 combine adds.

#define TT 200
#define BN 4096
#define HH 32

using ull = unsigned long long;

__device__ float g_scr[TT * BN];  // 3.3 MB scratch for backward dots

__device__ __forceinline__ ull pack2(float a, float b) {
    ull r; asm("mov.b64 %0, {%1, %2};" : "=l"(r) : "f"(a), "f"(b)); return r;
}
__device__ __forceinline__ ull fma2(ull a, ull b, ull c) {
    ull d; asm("fma.rn.f32x2 %0, %1, %2, %3;" : "=l"(d) : "l"(a), "l"(b), "l"(c)); return d;
}
__device__ __forceinline__ ull add2(ull a, ull b) {
    ull d; asm("add.rn.f32x2 %0, %1, %2;" : "=l"(d) : "l"(a), "l"(b)); return d;
}
__device__ __forceinline__ float hsum2(ull a) {
    float lo, hi; asm("mov.b64 {%0, %1}, %2;" : "=f"(lo), "=f"(hi) : "l"(a)); return lo + hi;
}
__device__ __forceinline__ float tanh_fast(float x) {
    float y; asm("tanh.approx.f32 %0, %1;" : "=f"(y) : "f"(x)); return y;
}
__device__ __forceinline__ float sigm(float x) {
    return fmaf(tanh_fast(0.5f * x), 0.5f, 0.5f);
}

__global__ __launch_bounds__(128, 3)
void gru_both(const float* __restrict__ x,
              const float* __restrict__ w_ih_f, const float* __restrict__ w_hh_f,
              const float* __restrict__ b_ih_f, const float* __restrict__ b_hh_f,
              const float* __restrict__ w_ih_b, const float* __restrict__ w_hh_b,
              const float* __restrict__ b_ih_b, const float* __restrict__ b_hh_b,
              const float* __restrict__ fc_w, const float* __restrict__ fc_b,
              float* __restrict__ out)
{
    __shared__ __align__(8) float hbuf[4][HH];   // per-warp h vector

    const int lane = threadIdx.x & 31;
    const int w    = threadIdx.x >> 5;
    const int gw   = blockIdx.x * 4 + w;        // 0..8191
    const int dir  = gw >> 12;                  // 0 fwd, 1 bwd
    const int b    = gw & (BN - 1);

    const float* w_ih = dir ? w_ih_b : w_ih_f;
    const float* w_hh = dir ? w_hh_b : w_hh_f;
    const float* b_ih = dir ? b_ih_b : b_ih_f;
    const float* b_hh = dir ? b_hh_b : b_hh_f;

    // SMEM addresses for this warp's h vector
    uint32_t sbase;
    asm("{ .reg .u64 t; cvta.to.shared.u64 t, %1; cvt.u32.u64 %0, t; }"
        : "=r"(sbase) : "l"((const void*)hbuf));
    const uint32_t hb      = sbase + (uint32_t)w * (HH * 4u);
    const uint32_t st_addr = hb + (lane << 2);

    // W_hh rows for this lane's three gates, packed pairs along j (row = 128B)
    const ull* pr = reinterpret_cast<const ull*>(w_hh + (size_t)lane * HH);
    const ull* pz = reinterpret_cast<const ull*>(w_hh + (size_t)(HH + lane) * HH);
    const ull* pn = reinterpret_cast<const ull*>(w_hh + (size_t)(2 * HH + lane) * HH);
    ull wr[16], wz[16], wn[16];
#pragma unroll
    for (int k = 0; k < 16; k++) { wr[k] = pr[k]; wz[k] = pz[k]; wn[k] = pn[k]; }

    const float wxr0 = w_ih[lane * 3 + 0], wxr1 = w_ih[lane * 3 + 1], wxr2 = w_ih[lane * 3 + 2];
    const float wxz0 = w_ih[(HH + lane) * 3 + 0], wxz1 = w_ih[(HH + lane) * 3 + 1], wxz2 = w_ih[(HH + lane) * 3 + 2];
    const float wxn0 = w_ih[(2 * HH + lane) * 3 + 0], wxn1 = w_ih[(2 * HH + lane) * 3 + 1], wxn2 = w_ih[(2 * HH + lane) * 3 + 2];

    const float br  = b_ih[lane] + b_hh[lane];
    const float bz  = b_ih[HH + lane] + b_hh[HH + lane];
    const float bxn = b_ih[2 * HH + lane];
    const float bhn = b_hh[2 * HH + lane];
    const float fcw = fc_w[dir * HH + lane];
    const float fcb = fc_b[0];

    float h = 0.f;
    asm volatile("st.shared.f32 [%0], %1;" :: "r"(st_addr), "f"(h) : "memory");

    // Prefetch x for first step
    const int t0 = dir ? (TT - 1) : 0;
    const float* xp = x + ((size_t)t0 * BN + b) * 3;
    float x0 = xp[0], x1 = xp[1], x2 = xp[2];

    for (int s = 0; s < TT; s++) {
        const int t  = dir ? (TT - 1 - s) : s;
        const int tn = dir ? (t > 0 ? t - 1 : 0) : (t < TT - 1 ? t + 1 : TT - 1);
        const float* xq = x + ((size_t)tn * BN + b) * 3;
        const float nx0 = xq[0], nx1 = xq[1], nx2 = xq[2];   // prefetch next step

        // input-gate preactivations; biases folded into accumulator inits
        const float xr = fmaf(wxr2, x2, fmaf(wxr1, x1, fmaf(wxr0, x0, br)));
        const float xz = fmaf(wxz2, x2, fmaf(wxz1, x1, fmaf(wxz0, x0, bz)));
        const float xn = fmaf(wxn2, x2, fmaf(wxn1, x1, fmaf(wxn0, x0, bxn)));

        // hg = W_hh @ h via broadcast LDS.64 (h pair feeds fma2 directly);
        // dual chains per gate
        ull ar0 = pack2(xr, 0.f), az0 = pack2(xz, 0.f), an0 = pack2(bhn, 0.f);
        ull ar1 = 0, az1 = 0, an1 = 0;
#pragma unroll
        for (int k = 0; k < 8; k++) {
            ull p0, p1;
            asm volatile("ld.shared.b64 %0, [%1];" : "=l"(p0) : "r"(hb + (2 * k)     * 8u));
            asm volatile("ld.shared.b64 %0, [%1];" : "=l"(p1) : "r"(hb + (2 * k + 1) * 8u));
            ar0 = fma2(wr[2 * k], p0, ar0);   ar1 = fma2(wr[2 * k + 1], p1, ar1);
            az0 = fma2(wz[2 * k], p0, az0);   az1 = fma2(wz[2 * k + 1], p1, az1);
            an0 = fma2(wn[2 * k], p0, an0);   an1 = fma2(wn[2 * k + 1], p1, an1);
        }

        const float pre_r = hsum2(add2(ar0, ar1));
        const float pre_z = hsum2(add2(az0, az1));
        const float hn    = hsum2(add2(an0, an1));

        const float r = sigm(pre_r);
        const float z = sigm(pre_z);
        const float n = tanh_fast(fmaf(r, hn, xn));
        h = fmaf(z, h - n, n);   // (1-z)*n + z*h

        asm volatile("st.shared.f32 [%0], %1;" :: "r"(st_addr), "f"(h) : "memory");

        // FC (C=1): 5-shfl butterfly, off the recurrence critical path
        float v = h * fcw;
#pragma unroll
        for (int m = 16; m >= 1; m >>= 1) v += __shfl_xor_sync(0xffffffffu, v, m);
        if (lane == 0) {
            const size_t oi = (size_t)t * BN + b;
            if (dir == 0) out[oi] = v + fcb;
            else          g_scr[oi] = v;
        }

        x0 = nx0; x1 = nx1; x2 = nx2;
    }
}

__global__ __launch_bounds__(256)
void combine_add(float* __restrict__ out)
{
    const int i = blockIdx.x * blockDim.x + threadIdx.x;   // 204800 float4s
    float4* o = reinterpret_cast<float4*>(out);
    const float4* s = reinterpret_cast<const float4*>(g_scr);
    float4 a = o[i];
    const float4 c = s[i];
    a.x += c.x; a.y += c.y; a.z += c.z; a.w += c.w;
    o[i] = a;
}

extern "C" void kernel_launch(void* const* d_in, const int* in_sizes, int n_in,
                              void* d_out, int out_size)
{
    (void)in_sizes; (void)n_in; (void)out_size;
    const float* x      = (const float*)d_in[0];
    const float* w_ih_f = (const float*)d_in[1];
    const float* w_hh_f = (const float*)d_in[2];
    const float* b_ih_f = (const float*)d_in[3];
    const float* b_hh_f = (const float*)d_in[4];
    const float* w_ih_b = (const float*)d_in[5];
    const float* w_hh_b = (const float*)d_in[6];
    const float* b_ih_b = (const float*)d_in[7];
    const float* b_hh_b = (const float*)d_in[8];
    const float* fc_w   = (const float*)d_in[9];
    const float* fc_b   = (const float*)d_in[10];
    float* out = (float*)d_out;

    gru_both<<<2048, 128>>>(x, w_ih_f, w_hh_f, b_ih_f, b_hh_f,
                            w_ih_b, w_hh_b, b_ih_b, b_hh_b, fc_w, fc_b, out);
    combine_add<<<(TT * BN / 4) / 256, 256>>>(out);
}

// round 7
// speedup vs baseline: 1.5578x; 1.0909x over previous
#include <cuda_runtime.h>
#include <cstddef>
#include <cstdint>

// GRU_13907104105002: bidirectional GRU (T=200,B=4096,I=3,H=32) + FC(C=1).
// R7: ILP-2 retry with R4's failure modes removed. warp = (dir, batch-pair),
// lane = hidden index. 2 batch streams per warp share the 96 weight registers.
// h broadcast via per-warp-per-stream SMEM, read as ld.shared.v2.b64 (16B/lane,
// feeds fma2 directly -> zero pack2). __launch_bounds__(128,2): 255 regs, no
// spills (R4 spilled under the 170 cap). x loads shared across the stream pair
// (float2). FC folded into a fused dual-tree 6-shfl reduction serving both
// streams. fwd writes out, bwd writes scratch, float4 combine adds.

#define TT 200
#define BN 4096
#define HH 32

using ull = unsigned long long;

__device__ float g_scr[TT * BN];  // 3.3 MB scratch for backward dots

__device__ __forceinline__ ull fma2(ull a, ull b, ull c) {
    ull d; asm("fma.rn.f32x2 %0, %1, %2, %3;" : "=l"(d) : "l"(a), "l"(b), "l"(c)); return d;
}
__device__ __forceinline__ ull add2(ull a, ull b) {
    ull d; asm("add.rn.f32x2 %0, %1, %2;" : "=l"(d) : "l"(a), "l"(b)); return d;
}
__device__ __forceinline__ ull pack2(float a, float b) {
    ull r; asm("mov.b64 %0, {%1, %2};" : "=l"(r) : "f"(a), "f"(b)); return r;
}
__device__ __forceinline__ float hsum2(ull a) {
    float lo, hi; asm("mov.b64 {%0, %1}, %2;" : "=f"(lo), "=f"(hi) : "l"(a)); return lo + hi;
}
__device__ __forceinline__ float tanh_fast(float x) {
    float y; asm("tanh.approx.f32 %0, %1;" : "=f"(y) : "f"(x)); return y;
}
__device__ __forceinline__ float sigm(float x) {
    return fmaf(tanh_fast(0.5f * x), 0.5f, 0.5f);
}

__global__ __launch_bounds__(128, 2)
void gru_both(const float* __restrict__ x,
              const float* __restrict__ w_ih_f, const float* __restrict__ w_hh_f,
              const float* __restrict__ b_ih_f, const float* __restrict__ b_hh_f,
              const float* __restrict__ w_ih_b, const float* __restrict__ w_hh_b,
              const float* __restrict__ b_ih_b, const float* __restrict__ b_hh_b,
              const float* __restrict__ fc_w, const float* __restrict__ fc_b,
              float* __restrict__ out)
{
    __shared__ __align__(16) float hbuf[4][2][HH];  // [warp][stream][hidden]

    const int lane = threadIdx.x & 31;
    const int w    = threadIdx.x >> 5;
    const int gw   = blockIdx.x * 4 + w;        // 0..4095 warps
    const int dir  = gw >> 11;                  // 2048 warp-pairs per direction
    const int bp   = gw & 2047;
    const int b0   = bp * 2;                    // even -> 8B-aligned x pairs

    const float* w_ih = dir ? w_ih_b : w_ih_f;
    const float* w_hh = dir ? w_hh_b : w_hh_f;
    const float* b_ih = dir ? b_ih_b : b_ih_f;
    const float* b_hh = dir ? b_hh_b : b_hh_f;

    uint32_t sbase;
    asm("{ .reg .u64 t; cvta.to.shared.u64 t, %1; cvt.u32.u64 %0, t; }"
        : "=r"(sbase) : "l"((const void*)hbuf));
    const uint32_t rA  = sbase + (uint32_t)w * 256u;   // stream-A h (128B)
    const uint32_t rB  = rA + 128u;                    // stream-B h (128B)
    const uint32_t stA = rA + (lane << 2);
    const uint32_t stB = rB + (lane << 2);

    // W_hh rows for this lane's three gates, packed pairs along j (row = 128B)
    const ull* pr = reinterpret_cast<const ull*>(w_hh + (size_t)lane * HH);
    const ull* pz = reinterpret_cast<const ull*>(w_hh + (size_t)(HH + lane) * HH);
    const ull* pn = reinterpret_cast<const ull*>(w_hh + (size_t)(2 * HH + lane) * HH);
    ull wr[16], wz[16], wn[16];
#pragma unroll
    for (int k = 0; k < 16; k++) { wr[k] = pr[k]; wz[k] = pz[k]; wn[k] = pn[k]; }

    const float wxr0 = w_ih[lane * 3 + 0], wxr1 = w_ih[lane * 3 + 1], wxr2 = w_ih[lane * 3 + 2];
    const float wxz0 = w_ih[(HH + lane) * 3 + 0], wxz1 = w_ih[(HH + lane) * 3 + 1], wxz2 = w_ih[(HH + lane) * 3 + 2];
    const float wxn0 = w_ih[(2 * HH + lane) * 3 + 0], wxn1 = w_ih[(2 * HH + lane) * 3 + 1], wxn2 = w_ih[(2 * HH + lane) * 3 + 2];

    const float br  = b_ih[lane] + b_hh[lane];
    const float bz  = b_ih[HH + lane] + b_hh[HH + lane];
    const float bxn = b_ih[2 * HH + lane];
    const float bhn = b_hh[2 * HH + lane];
    const float fcw = fc_w[dir * HH + lane];
    const float fcb = fc_b[0];

    float h0 = 0.f, h1 = 0.f;
    asm volatile("st.shared.f32 [%0], %1;" :: "r"(stA), "f"(h0) : "memory");
    asm volatile("st.shared.f32 [%0], %1;" :: "r"(stB), "f"(h1) : "memory");

    // Prefetch x for first step: 6 floats (both streams) via 3 float2
    const int tf = dir ? (TT - 1) : 0;
    const float2* xq0 = reinterpret_cast<const float2*>(x + ((size_t)tf * BN + b0) * 3);
    float2 e0 = xq0[0], e1 = xq0[1], e2 = xq0[2];

    for (int s = 0; s < TT; s++) {
        const int t  = dir ? (TT - 1 - s) : s;
        const int tn = dir ? (t > 0 ? t - 1 : 0) : (t < TT - 1 ? t + 1 : TT - 1);
        const float2* xq = reinterpret_cast<const float2*>(x + ((size_t)tn * BN + b0) * 3);
        const float2 f0 = xq[0], f1 = xq[1], f2 = xq[2];  // prefetch next step

        // current x: stream A = (e0.x,e0.y,e1.x), stream B = (e1.y,e2.x,e2.y)
        const float xa0 = e0.x, xa1 = e0.y, xa2 = e1.x;
        const float xb0 = e1.y, xb1 = e2.x, xb2 = e2.y;

        const float xra = fmaf(wxr2, xa2, fmaf(wxr1, xa1, fmaf(wxr0, xa0, br)));
        const float xza = fmaf(wxz2, xa2, fmaf(wxz1, xa1, fmaf(wxz0, xa0, bz)));
        const float xna = fmaf(wxn2, xa2, fmaf(wxn1, xa1, fmaf(wxn0, xa0, bxn)));
        const float xrb = fmaf(wxr2, xb2, fmaf(wxr1, xb1, fmaf(wxr0, xb0, br)));
        const float xzb = fmaf(wxz2, xb2, fmaf(wxz1, xb1, fmaf(wxz0, xb0, bz)));
        const float xnb = fmaf(wxn2, xb2, fmaf(wxn1, xb1, fmaf(wxn0, xb0, bxn)));

        // accumulators: dual chains per gate per stream, biases/ih folded in
        ull arA0 = pack2(xra, 0.f), azA0 = pack2(xza, 0.f), anA0 = pack2(bhn, 0.f);
        ull arA1 = 0, azA1 = 0, anA1 = 0;
        ull arB0 = pack2(xrb, 0.f), azB0 = pack2(xzb, 0.f), anB0 = pack2(bhn, 0.f);
        ull arB1 = 0, azB1 = 0, anB1 = 0;

#pragma unroll
        for (int k = 0; k < 8; k++) {
            ull pa0, pa1, pb0, pb1;
            asm volatile("ld.shared.v2.b64 {%0,%1}, [%2];"
                         : "=l"(pa0), "=l"(pa1) : "r"(rA + k * 16u));
            asm volatile("ld.shared.v2.b64 {%0,%1}, [%2];"
                         : "=l"(pb0), "=l"(pb1) : "r"(rB + k * 16u));
            const ull w0r = wr[2 * k], w1r = wr[2 * k + 1];
            const ull w0z = wz[2 * k], w1z = wz[2 * k + 1];
            const ull w0n = wn[2 * k], w1n = wn[2 * k + 1];
            arA0 = fma2(w0r, pa0, arA0);  arA1 = fma2(w1r, pa1, arA1);
            arB0 = fma2(w0r, pb0, arB0);  arB1 = fma2(w1r, pb1, arB1);
            azA0 = fma2(w0z, pa0, azA0);  azA1 = fma2(w1z, pa1, azA1);
            azB0 = fma2(w0z, pb0, azB0);  azB1 = fma2(w1z, pb1, azB1);
            anA0 = fma2(w0n, pa0, anA0);  anA1 = fma2(w1n, pa1, anA1);
            anB0 = fma2(w0n, pb0, anB0);  anB1 = fma2(w1n, pb1, anB1);
        }

        // stream A
        {
            const float r = sigm(hsum2(add2(arA0, arA1)));
            const float z = sigm(hsum2(add2(azA0, azA1)));
            const float n = tanh_fast(fmaf(r, hsum2(add2(anA0, anA1)), xna));
            h0 = fmaf(z, h0 - n, n);
        }
        // stream B
        {
            const float r = sigm(hsum2(add2(arB0, arB1)));
            const float z = sigm(hsum2(add2(azB0, azB1)));
            const float n = tanh_fast(fmaf(r, hsum2(add2(anB0, anB1)), xnb));
            h1 = fmaf(z, h1 - n, n);
        }

        asm volatile("st.shared.f32 [%0], %1;" :: "r"(stA), "f"(h0) : "memory");
        asm volatile("st.shared.f32 [%0], %1;" :: "r"(stB), "f"(h1) : "memory");

        // FC: fused dual-tree — 6 shfl reduce both streams.
        {
            const float v0 = h0 * fcw;
            const float v1 = h1 * fcw;
            const float o0 = __shfl_xor_sync(0xffffffffu, v0, 16);
            const float o1 = __shfl_xor_sync(0xffffffffu, v1, 16);
            float c = (lane < 16) ? (v0 + o0) : (v1 + o1);
#pragma unroll
            for (int m = 8; m >= 1; m >>= 1) c += __shfl_xor_sync(0xffffffffu, c, m);
            if ((lane & 15) == 0) {
                const size_t oi = (size_t)t * BN + b0 + (lane >> 4);
                if (dir == 0) out[oi] = c + fcb;
                else          g_scr[oi] = c;
            }
        }

        e0 = f0; e1 = f1; e2 = f2;
    }
}

__global__ __launch_bounds__(256)
void combine_add(float* __restrict__ out)
{
    const int i = blockIdx.x * blockDim.x + threadIdx.x;   // 204800 float4s
    float4* o = reinterpret_cast<float4*>(out);
    const float4* s = reinterpret_cast<const float4*>(g_scr);
    float4 a = o[i];
    const float4 c = s[i];
    a.x += c.x; a.y += c.y; a.z += c.z; a.w += c.w;
    o[i] = a;
}

extern "C" void kernel_launch(void* const* d_in, const int* in_sizes, int n_in,
                              void* d_out, int out_size)
{
    (void)in_sizes; (void)n_in; (void)out_size;
    const float* x      = (const float*)d_in[0];
    const float* w_ih_f = (const float*)d_in[1];
    const float* w_hh_f = (const float*)d_in[2];
    const float* b_ih_f = (const float*)d_in[3];
    const float* b_hh_f = (const float*)d_in[4];
    const float* w_ih_b = (const float*)d_in[5];
    const float* w_hh_b = (const float*)d_in[6];
    const float* b_ih_b = (const float*)d_in[7];
    const float* b_hh_b = (const float*)d_in[8];
    const float* fc_w   = (const float*)d_in[9];
    const float* fc_b   = (const float*)d_in[10];
    float* out = (float*)d_out;

    gru_both<<<1024, 128>>>(x, w_ih_f, w_hh_f, b_ih_f, b_hh_f,
                            w_ih_b, w_hh_b, b_ih_b, b_hh_b, fc_w, fc_b, out);
    combine_add<<<(TT * BN / 4) / 256, 256>>>(out);
}

// round 8
// speedup vs baseline: 1.6295x; 1.0460x over previous
#include <cuda_runtime.h>
#include <cstddef>
#include <cstdint>

// GRU_13907104105002: bidirectional GRU (T=200,B=4096,I=3,H=32) + FC(C=1).
// R8: ILP-4. warp = (dir, batch-quad), lane = hidden index. 4 batch streams
// per warp share the 96 weight registers -> 8 streams/SMSP at 2 blocks/SM to
// hide the ~130-cyc step chain (R7 measured 40% dead issue at 4 streams).
// h broadcast via per-warp-per-stream SMEM, ld.shared.v4.f32 (8 LDS.128 per
// batch-step = bandwidth minimum). Single fused fma2 chain per gate per stream
// (3 ull accums/stream) to stay under the 256-reg cap. x for the quad loads as
// 3x LDG.128 (b0 % 4 == 0 -> 16B aligned), double-buffered. FC = two fused
// dual-tree reductions (12 shfl/warp-step). fwd writes out, bwd writes
// scratch, float4 combine adds.

#define TT 200
#define BN 4096
#define HH 32

using ull = unsigned long long;

__device__ float g_scr[TT * BN];  // 3.3 MB scratch for backward dots

__device__ __forceinline__ ull pack2(float a, float b) {
    ull r; asm("mov.b64 %0, {%1, %2};" : "=l"(r) : "f"(a), "f"(b)); return r;
}
__device__ __forceinline__ ull fma2(ull a, ull b, ull c) {
    ull d; asm("fma.rn.f32x2 %0, %1, %2, %3;" : "=l"(d) : "l"(a), "l"(b), "l"(c)); return d;
}
__device__ __forceinline__ float hsum2(ull a) {
    float lo, hi; asm("mov.b64 {%0, %1}, %2;" : "=f"(lo), "=f"(hi) : "l"(a)); return lo + hi;
}
__device__ __forceinline__ float tanh_fast(float x) {
    float y; asm("tanh.approx.f32 %0, %1;" : "=f"(y) : "f"(x)); return y;
}
__device__ __forceinline__ float sigm(float x) {
    return fmaf(tanh_fast(0.5f * x), 0.5f, 0.5f);
}

__global__ __launch_bounds__(128, 2)
void gru_both(const float* __restrict__ x,
              const float* __restrict__ w_ih_f, const float* __restrict__ w_hh_f,
              const float* __restrict__ b_ih_f, const float* __restrict__ b_hh_f,
              const float* __restrict__ w_ih_b, const float* __restrict__ w_hh_b,
              const float* __restrict__ b_ih_b, const float* __restrict__ b_hh_b,
              const float* __restrict__ fc_w, const float* __restrict__ fc_b,
              float* __restrict__ out)
{
    __shared__ __align__(16) float hbuf[4][4][HH];  // [warp][stream][hidden]

    const int lane = threadIdx.x & 31;
    const int w    = threadIdx.x >> 5;
    const int gw   = blockIdx.x * 4 + w;        // 0..2047
    const int dir  = gw >> 10;                  // 1024 warps per direction
    const int qp   = gw & 1023;
    const int b0   = qp * 4;                    // quad base; 16B-aligned x rows

    const float* w_ih = dir ? w_ih_b : w_ih_f;
    const float* w_hh = dir ? w_hh_b : w_hh_f;
    const float* b_ih = dir ? b_ih_b : b_ih_f;
    const float* b_hh = dir ? b_hh_b : b_hh_f;

    uint32_t sbase;
    asm("{ .reg .u64 t; cvta.to.shared.u64 t, %1; cvt.u32.u64 %0, t; }"
        : "=r"(sbase) : "l"((const void*)hbuf));
    uint32_t hreg[4];
#pragma unroll
    for (int m = 0; m < 4; m++) hreg[m] = sbase + (uint32_t)w * 512u + (uint32_t)m * 128u;

    // W_hh rows for this lane's three gates, packed pairs along j (row = 128B)
    const ull* pr = reinterpret_cast<const ull*>(w_hh + (size_t)lane * HH);
    const ull* pz = reinterpret_cast<const ull*>(w_hh + (size_t)(HH + lane) * HH);
    const ull* pn = reinterpret_cast<const ull*>(w_hh + (size_t)(2 * HH + lane) * HH);
    ull wr[16], wz[16], wn[16];
#pragma unroll
    for (int k = 0; k < 16; k++) { wr[k] = pr[k]; wz[k] = pz[k]; wn[k] = pn[k]; }

    const float wxr0 = w_ih[lane * 3 + 0], wxr1 = w_ih[lane * 3 + 1], wxr2 = w_ih[lane * 3 + 2];
    const float wxz0 = w_ih[(HH + lane) * 3 + 0], wxz1 = w_ih[(HH + lane) * 3 + 1], wxz2 = w_ih[(HH + lane) * 3 + 2];
    const float wxn0 = w_ih[(2 * HH + lane) * 3 + 0], wxn1 = w_ih[(2 * HH + lane) * 3 + 1], wxn2 = w_ih[(2 * HH + lane) * 3 + 2];

    const float br  = b_ih[lane] + b_hh[lane];
    const float bz  = b_ih[HH + lane] + b_hh[HH + lane];
    const float bxn = b_ih[2 * HH + lane];
    const float bhn = b_hh[2 * HH + lane];
    const float fcw = fc_w[dir * HH + lane];
    const float fcb = fc_b[0];

    float h[4] = {0.f, 0.f, 0.f, 0.f};
#pragma unroll
    for (int m = 0; m < 4; m++)
        asm volatile("st.shared.f32 [%0], %1;" :: "r"(hreg[m] + (lane << 2)), "f"(h[m]) : "memory");

    // Prefetch x for the first step: 12 floats (4 batches) via 3x float4
    const int tf = dir ? (TT - 1) : 0;
    const float4* xq0 = reinterpret_cast<const float4*>(x + ((size_t)tf * BN + b0) * 3);
    float4 X0 = xq0[0], X1 = xq0[1], X2 = xq0[2];

    for (int s = 0; s < TT; s++) {
        const int t  = dir ? (TT - 1 - s) : s;
        const int tn = dir ? (t > 0 ? t - 1 : 0) : (t < TT - 1 ? t + 1 : TT - 1);

        // per-stream x triples from the 3 quads
        const float xs[4][3] = {
            {X0.x, X0.y, X0.z}, {X0.w, X1.x, X1.y},
            {X1.z, X1.w, X2.x}, {X2.y, X2.z, X2.w}};

        // input-gate preactivations (release X quads, then prefetch next)
        float xr[4], xz[4], xn[4];
#pragma unroll
        for (int m = 0; m < 4; m++) {
            xr[m] = fmaf(wxr2, xs[m][2], fmaf(wxr1, xs[m][1], fmaf(wxr0, xs[m][0], br)));
            xz[m] = fmaf(wxz2, xs[m][2], fmaf(wxz1, xs[m][1], fmaf(wxz0, xs[m][0], bz)));
            xn[m] = fmaf(wxn2, xs[m][2], fmaf(wxn1, xs[m][1], fmaf(wxn0, xs[m][0], bxn)));
        }
        const float4* xq = reinterpret_cast<const float4*>(x + ((size_t)tn * BN + b0) * 3);
        X0 = xq[0]; X1 = xq[1]; X2 = xq[2];

        // accumulators: single fused chain per gate per stream
        ull ar[4], az[4], an[4];
#pragma unroll
        for (int m = 0; m < 4; m++) {
            ar[m] = pack2(xr[m], 0.f);
            az[m] = pack2(xz[m], 0.f);
            an[m] = pack2(bhn, 0.f);
        }

#pragma unroll
        for (int k = 0; k < 8; k++) {
#pragma unroll
            for (int m = 0; m < 4; m++) {
                float q0, q1, q2, q3;
                asm volatile("ld.shared.v4.f32 {%0,%1,%2,%3}, [%4];"
                             : "=f"(q0), "=f"(q1), "=f"(q2), "=f"(q3)
                             : "r"(hreg[m] + k * 16u));
                const ull p0 = pack2(q0, q1);
                const ull p1 = pack2(q2, q3);
                ar[m] = fma2(wr[2 * k + 1], p1, fma2(wr[2 * k], p0, ar[m]));
                az[m] = fma2(wz[2 * k + 1], p1, fma2(wz[2 * k], p0, az[m]));
                an[m] = fma2(wn[2 * k + 1], p1, fma2(wn[2 * k], p0, an[m]));
            }
        }

#pragma unroll
        for (int m = 0; m < 4; m++) {
            const float r = sigm(hsum2(ar[m]));
            const float z = sigm(hsum2(az[m]));
            const float n = tanh_fast(fmaf(r, hsum2(an[m]), xn[m]));
            h[m] = fmaf(z, h[m] - n, n);   // (1-z)*n + z*h
            asm volatile("st.shared.f32 [%0], %1;" :: "r"(hreg[m] + (lane << 2)), "f"(h[m]) : "memory");
        }

        // FC (C=1): two fused dual-tree reductions (streams 0/1 and 2/3)
        {
            const float v0 = h[0] * fcw, v1 = h[1] * fcw;
            const float v2 = h[2] * fcw, v3 = h[3] * fcw;
            const float o0 = __shfl_xor_sync(0xffffffffu, v0, 16);
            const float o1 = __shfl_xor_sync(0xffffffffu, v1, 16);
            const float o2 = __shfl_xor_sync(0xffffffffu, v2, 16);
            const float o3 = __shfl_xor_sync(0xffffffffu, v3, 16);
            float c1 = (lane < 16) ? (v0 + o0) : (v1 + o1);
            float c2 = (lane < 16) ? (v2 + o2) : (v3 + o3);
#pragma unroll
            for (int m2 = 8; m2 >= 1; m2 >>= 1) {
                c1 += __shfl_xor_sync(0xffffffffu, c1, m2);
                c2 += __shfl_xor_sync(0xffffffffu, c2, m2);
            }
            if ((lane & 15) == 0) {
                const size_t oi = (size_t)t * BN + b0 + (lane >> 4);
                if (dir == 0) { out[oi] = c1 + fcb;  out[oi + 2] = c2 + fcb; }
                else          { g_scr[oi] = c1;      g_scr[oi + 2] = c2; }
            }
        }
    }
}

__global__ __launch_bounds__(256)
void combine_add(float* __restrict__ out)
{
    const int i = blockIdx.x * blockDim.x + threadIdx.x;   // 204800 float4s
    float4* o = reinterpret_cast<float4*>(out);
    const float4* s = reinterpret_cast<const float4*>(g_scr);
    float4 a = o[i];
    const float4 c = s[i];
    a.x += c.x; a.y += c.y; a.z += c.z; a.w += c.w;
    o[i] = a;
}

extern "C" void kernel_launch(void* const* d_in, const int* in_sizes, int n_in,
                              void* d_out, int out_size)
{
    (void)in_sizes; (void)n_in; (void)out_size;
    const float* x      = (const float*)d_in[0];
    const float* w_ih_f = (const float*)d_in[1];
    const float* w_hh_f = (const float*)d_in[2];
    const float* b_ih_f = (const float*)d_in[3];
    const float* b_hh_f = (const float*)d_in[4];
    const float* w_ih_b = (const float*)d_in[5];
    const float* w_hh_b = (const float*)d_in[6];
    const float* b_ih_b = (const float*)d_in[7];
    const float* b_hh_b = (const float*)d_in[8];
    const float* fc_w   = (const float*)d_in[9];
    const float* fc_b   = (const float*)d_in[10];
    float* out = (float*)d_out;

    gru_both<<<512, 128>>>(x, w_ih_f, w_hh_f, b_ih_f, b_hh_f,
                           w_ih_b, w_hh_b, b_ih_b, b_hh_b, fc_w, fc_b, out);
    combine_add<<<(TT * BN / 4) / 256, 256>>>(out);
}

// round 10
// speedup vs baseline: 3.9516x; 2.4250x over previous
#include <cuda_runtime.h>
#include <cuda_fp16.h>
#include <cstdint>
#include <cstddef>

// GRU_13907104105002 — R10: legacy-HMMA (mma.sync.m16n8k16) recurrence.
// tcgen05 is unavailable (harness emits compute_103 PTX, not 103a); mma.sync
// is base-ISA. Key identity: D-fragment layout (m16n8 f32) maps thread-
// identically onto next step's A-fragment K slots -> h stays in registers
// across the whole recurrence. No smem, no shuffle broadcast, no syncs.
//
// Warp = 16 batches x 1 dir. N=128 gate cols: [r|z|hn|xn] (4 tiles each).
// K passes per step: h_hi x2 + h_lo x2 (f16 residual of h, reusing the same
// B regs -> cancels recurrent h-quantization error) + x-tile x1 (x_hi 3, 1.0
// bias slot, x_lo 3 -> cancels x quantization). Weights/biases f16 in B
// fragments (64 regs, loaded once). FC(C=1) = 16 local FMAs + 2 shfl.
// fwd writes out, bwd writes scratch, float4 combine adds.

#define TT 200
#define BN 4096
#define HH 32

__device__ float g_scr[TT * BN];

__device__ __forceinline__ float tanh_fast(float x) {
    float y; asm("tanh.approx.f32 %0, %1;" : "=f"(y) : "f"(x)); return y;
}
__device__ __forceinline__ float sigm(float x) {
    return fmaf(tanh_fast(0.5f * x), 0.5f, 0.5f);
}
// pack {low=a, high=b} as f16x2
__device__ __forceinline__ uint32_t h2pack(float a, float b) {
    uint32_t d; asm("cvt.rn.f16x2.f32 %0, %1, %2;" : "=r"(d) : "f"(b), "f"(a)); return d;
}
// f16x2 -> two floats
__device__ __forceinline__ float2 h2unpack(uint32_t v) {
    __half2 h = *reinterpret_cast<__half2*>(&v);
    return __half22float2(h);
}
__device__ __forceinline__ void mma16816(float* d,
                                         uint32_t a0, uint32_t a1, uint32_t a2, uint32_t a3,
                                         uint32_t b0, uint32_t b1,
                                         const float* c) {
    asm volatile("mma.sync.aligned.m16n8k16.row.col.f32.f16.f16.f32 "
                 "{%0,%1,%2,%3}, {%4,%5,%6,%7}, {%8,%9}, {%10,%11,%12,%13};"
                 : "=f"(d[0]), "=f"(d[1]), "=f"(d[2]), "=f"(d[3])
                 : "r"(a0), "r"(a1), "r"(a2), "r"(a3), "r"(b0), "r"(b1),
                   "f"(c[0]), "f"(c[1]), "f"(c[2]), "f"(c[3]));
}

__global__ __launch_bounds__(128, 1)
void gru_mma(const float* __restrict__ x,
             const float* __restrict__ w_ih_f, const float* __restrict__ w_hh_f,
             const float* __restrict__ b_ih_f, const float* __restrict__ b_hh_f,
             const float* __restrict__ w_ih_b, const float* __restrict__ w_hh_b,
             const float* __restrict__ b_ih_b, const float* __restrict__ b_hh_b,
             const float* __restrict__ fc_w, const float* __restrict__ fc_b,
             float* __restrict__ out)
{
    const int lane = threadIdx.x & 31;
    const int g    = lane >> 2;          // 0..7  (row group / B col)
    const int tg   = lane & 3;           // 0..3  (thread-in-group)
    const int gw   = blockIdx.x * 4 + (threadIdx.x >> 5);   // 0..511
    const int dir  = gw >> 8;            // 256 warps per direction
    const int wb   = (gw & 255) * 16;    // batch base of this warp's 16 rows

    const float* w_ih = dir ? w_ih_b : w_ih_f;
    const float* w_hh = dir ? w_hh_b : w_hh_f;
    const float* b_ih = dir ? b_ih_b : b_ih_f;
    const float* b_hh = dir ? b_hh_b : b_hh_f;

    // ---- B fragments (weights), loaded once ----
    // Bh[nt][kp][.] for N-tiles 0..11 (r 0-3, z 4-7, hn 8-11), K-pass kp=0,1
    // Bx[nt] (b0 of x-tile; b1 is always 0) for all 16 N-tiles.
    uint32_t Bh[12][2][2];
#pragma unroll
    for (int nt = 0; nt < 12; nt++) {
        const int G = nt >> 2;
        const int hcol = (nt & 3) * 8 + g;
        const int grow = G * 32 + hcol;
#pragma unroll
        for (int kp = 0; kp < 2; kp++) {
            const int kb = kp * 16;
            Bh[nt][kp][0] = h2pack(w_hh[grow * 32 + kb + 2 * tg],
                                   w_hh[grow * 32 + kb + 2 * tg + 1]);
            Bh[nt][kp][1] = h2pack(w_hh[grow * 32 + kb + 2 * tg + 8],
                                   w_hh[grow * 32 + kb + 2 * tg + 9]);
        }
    }
    uint32_t Bx[16];
#pragma unroll
    for (int nt = 0; nt < 16; nt++) {
        const int G = nt >> 2;
        const int hcol = (nt & 3) * 8 + g;
        float wi0 = 0.f, wi1 = 0.f, wi2 = 0.f, bias;
        if (G == 0) {
            wi0 = w_ih[hcol * 3]; wi1 = w_ih[hcol * 3 + 1]; wi2 = w_ih[hcol * 3 + 2];
            bias = b_ih[hcol] + b_hh[hcol];
        } else if (G == 1) {
            const int r = 32 + hcol;
            wi0 = w_ih[r * 3]; wi1 = w_ih[r * 3 + 1]; wi2 = w_ih[r * 3 + 2];
            bias = b_ih[r] + b_hh[r];
        } else if (G == 2) {
            bias = b_hh[64 + hcol];                       // hn hidden bias
        } else {
            const int r = 64 + hcol;
            wi0 = w_ih[r * 3]; wi1 = w_ih[r * 3 + 1]; wi2 = w_ih[r * 3 + 2];
            bias = b_ih[r];                               // xn input bias
        }
        // x-tile k slots: 0-2 = w, 3 = bias (A slot=1.0), 4-6 = w (residual), 7 = 0
        Bx[nt] = (tg == 0) ? h2pack(wi0, wi1)
               : (tg == 1) ? h2pack(wi2, bias)
               : (tg == 2) ? h2pack(wi0, wi1)
                           : h2pack(wi2, 0.f);
    }

    // fc weights for this thread's hidden columns (8j + 2tg, +1)
    float fw[4][2];
#pragma unroll
    for (int j = 0; j < 4; j++) {
        fw[j][0] = fc_w[dir * HH + 8 * j + 2 * tg];
        fw[j][1] = fc_w[dir * HH + 8 * j + 2 * tg + 1];
    }
    const float fcb = fc_b[0];

    // h state: hh[j][p]  p: 0=(g,2tg) 1=(g,2tg+1) 2=(g+8,2tg) 3=(g+8,2tg+1)
    float hh[4][4];
#pragma unroll
    for (int j = 0; j < 4; j++)
#pragma unroll
        for (int p = 0; p < 4; p++) hh[j][p] = 0.f;
    // A h fragments (hi + lo residual), start at zero
    uint32_t Ah[2][4], Al[2][4];
#pragma unroll
    for (int kt = 0; kt < 2; kt++)
#pragma unroll
        for (int q = 0; q < 4; q++) { Ah[kt][q] = 0u; Al[kt][q] = 0u; }

    // x for this thread's two batch rows (g, g+8), prefetched
    const int tf = dir ? (TT - 1) : 0;
    float xa0, xa1, xa2, xb0, xb1, xb2;
    {
        const float* p0 = x + ((size_t)tf * BN + wb + g) * 3;
        const float* p1 = x + ((size_t)tf * BN + wb + g + 8) * 3;
        xa0 = p0[0]; xa1 = p0[1]; xa2 = p0[2];
        xb0 = p1[0]; xb1 = p1[1]; xb2 = p1[2];
    }

    const float zc[4] = {0.f, 0.f, 0.f, 0.f};

#pragma unroll 1
    for (int s = 0; s < TT; s++) {
        const int t = dir ? (TT - 1 - s) : s;

        // ---- A x-tile fragment (hi + residual lo in one tile) ----
        uint32_t ax0, ax1;
        {
            float la0, la1, la2, lb0, lb1, lb2;
            {   // residuals: x - f16(x)
                float2 u;
                u = h2unpack(h2pack(xa0, xa1)); la0 = xa0 - u.x; la1 = xa1 - u.y;
                u = h2unpack(h2pack(xa2, xb0)); la2 = xa2 - u.x; lb0 = xb0 - u.y;
                u = h2unpack(h2pack(xb1, xb2)); lb1 = xb1 - u.x; lb2 = xb2 - u.y;
            }
            ax0 = (tg == 0) ? h2pack(xa0, xa1)
                : (tg == 1) ? h2pack(xa2, 1.f)
                : (tg == 2) ? h2pack(la0, la1)
                            : h2pack(la2, 0.f);
            ax1 = (tg == 0) ? h2pack(xb0, xb1)
                : (tg == 1) ? h2pack(xb2, 1.f)
                : (tg == 2) ? h2pack(lb0, lb1)
                            : h2pack(lb2, 0.f);
        }

        // ---- MMA chain: D[16][4] ----
        float D[16][4];
#pragma unroll
        for (int nt = 0; nt < 16; nt++)
            mma16816(D[nt], ax0, ax1, 0u, 0u, Bx[nt], 0u, zc);
#pragma unroll
        for (int nt = 0; nt < 12; nt++) {
            mma16816(D[nt], Ah[0][0], Ah[0][1], Ah[0][2], Ah[0][3], Bh[nt][0][0], Bh[nt][0][1], D[nt]);
            mma16816(D[nt], Ah[1][0], Ah[1][1], Ah[1][2], Ah[1][3], Bh[nt][1][0], Bh[nt][1][1], D[nt]);
            mma16816(D[nt], Al[0][0], Al[0][1], Al[0][2], Al[0][3], Bh[nt][0][0], Bh[nt][0][1], D[nt]);
            mma16816(D[nt], Al[1][0], Al[1][1], Al[1][2], Al[1][3], Bh[nt][1][0], Bh[nt][1][1], D[nt]);
        }

        // prefetch next x
        const int tn = dir ? (t > 0 ? t - 1 : 0) : (t < TT - 1 ? t + 1 : t);
        {
            const float* p0 = x + ((size_t)tn * BN + wb + g) * 3;
            const float* p1 = x + ((size_t)tn * BN + wb + g + 8) * 3;
            xa0 = p0[0]; xa1 = p0[1]; xa2 = p0[2];
            xb0 = p1[0]; xb1 = p1[1]; xb2 = p1[2];
        }

        // ---- epilogue: gates, h update, FC partials ----
        float v0 = 0.f, v1 = 0.f;   // rows g, g+8
#pragma unroll
        for (int j = 0; j < 4; j++) {
#pragma unroll
            for (int p = 0; p < 4; p++) {
                const float r = sigm(D[j][p]);
                const float z = sigm(D[4 + j][p]);
                const float n = tanh_fast(fmaf(r, D[8 + j][p], D[12 + j][p]));
                const float hv = fmaf(z, hh[j][p] - n, n);
                hh[j][p] = hv;
                const float c = hv * fw[j][p & 1];
                if (p < 2) v0 += c; else v1 += c;
            }
        }

        // ---- rebuild A h fragments (hi) + residual (lo) ----
#pragma unroll
        for (int kt = 0; kt < 2; kt++) {
#pragma unroll
            for (int q = 0; q < 4; q++) {
                const int j = kt * 2 + (q >> 1);
                const int p = (q & 1) * 2;
                const float a = hh[j][p], b = hh[j][p + 1];
                const uint32_t hi = h2pack(a, b);
                Ah[kt][q] = hi;
                const float2 u = h2unpack(hi);
                Al[kt][q] = h2pack(a - u.x, b - u.y);
            }
        }
        // fix A slot ordering: a0,a1 = rows g,g+8 of K-lo half; a2,a3 = K-hi half
        // (mapping above: q0=(j even, rows g), q1=(j even, rows g+8),
        //  q2=(j odd, rows g), q3=(j odd, rows g+8)) -- matches m16n8k16 A:
        //  a0:(g, 2tg..), a1:(g+8, 2tg..), a2:(g, 2tg+8..), a3:(g+8, 2tg+8..)

        // ---- FC reduce over the 4-lane group and write ----
        v0 += __shfl_xor_sync(0xffffffffu, v0, 1);
        v0 += __shfl_xor_sync(0xffffffffu, v0, 2);
        v1 += __shfl_xor_sync(0xffffffffu, v1, 1);
        v1 += __shfl_xor_sync(0xffffffffu, v1, 2);
        if (tg == 0) {
            const size_t o0 = (size_t)t * BN + wb + g;
            if (dir == 0) { out[o0] = v0 + fcb; out[o0 + 8] = v1 + fcb; }
            else          { g_scr[o0] = v0;     g_scr[o0 + 8] = v1; }
        }
    }
}

__global__ __launch_bounds__(256)
void combine_add(float* __restrict__ out)
{
    const int i = blockIdx.x * blockDim.x + threadIdx.x;   // 204800 float4s
    float4* o = reinterpret_cast<float4*>(out);
    const float4* s = reinterpret_cast<const float4*>(g_scr);
    float4 a = o[i];
    const float4 c = s[i];
    a.x += c.x; a.y += c.y; a.z += c.z; a.w += c.w;
    o[i] = a;
}

extern "C" void kernel_launch(void* const* d_in, const int* in_sizes, int n_in,
                              void* d_out, int out_size)
{
    (void)in_sizes; (void)n_in; (void)out_size;
    const float* x      = (const float*)d_in[0];
    const float* w_ih_f = (const float*)d_in[1];
    const float* w_hh_f = (const float*)d_in[2];
    const float* b_ih_f = (const float*)d_in[3];
    const float* b_hh_f = (const float*)d_in[4];
    const float* w_ih_b = (const float*)d_in[5];
    const float* w_hh_b = (const float*)d_in[6];
    const float* b_ih_b = (const float*)d_in[7];
    const float* b_hh_b = (const float*)d_in[8];
    const float* fc_w   = (const float*)d_in[9];
    const float* fc_b   = (const float*)d_in[10];
    float* out = (float*)d_out;

    gru_mma<<<128, 128>>>(x, w_ih_f, w_hh_f, b_ih_f, b_hh_f,
                          w_ih_b, w_hh_b, b_ih_b, b_hh_b, fc_w, fc_b, out);
    combine_add<<<(TT * BN / 4) / 256, 256>>>(out);
}

// round 11
// speedup vs baseline: 4.7562x; 1.2036x over previous
#include <cuda_runtime.h>
#include <cuda_fp16.h>
#include <cstdint>
#include <cstddef>

// GRU_13907104105002 — R11: HMMA recurrence, MMA count 64 -> 44.
// (R10 structure: warp = 16 batches x 1 dir, h lives in MMA fragments,
//  D-fragment layout == next-step A-fragment layout, no smem/shfl on h path.)
// R11 changes:
//  - h-residual (Al) passes only on the hn gate (tanh slope 1); r,z take the
//    sigmoid-damped h-quantization error (~1e-4): -16 MMAs.
//  - hn bias enters via accumulator init (C = b_hh broadcast), dropping the
//    hn x-tile MMAs that carried only the bias: -4 MMAs.
// fwd writes out, bwd writes scratch, float4 combine adds.

#define TT 200
#define BN 4096
#define HH 32

__device__ float g_scr[TT * BN];

__device__ __forceinline__ float tanh_fast(float x) {
    float y; asm("tanh.approx.f32 %0, %1;" : "=f"(y) : "f"(x)); return y;
}
__device__ __forceinline__ float sigm(float x) {
    return fmaf(tanh_fast(0.5f * x), 0.5f, 0.5f);
}
// pack {low=a, high=b} as f16x2
__device__ __forceinline__ uint32_t h2pack(float a, float b) {
    uint32_t d; asm("cvt.rn.f16x2.f32 %0, %1, %2;" : "=r"(d) : "f"(b), "f"(a)); return d;
}
__device__ __forceinline__ float2 h2unpack(uint32_t v) {
    __half2 h = *reinterpret_cast<__half2*>(&v);
    return __half22float2(h);
}
__device__ __forceinline__ void mma16816(float* d,
                                         uint32_t a0, uint32_t a1, uint32_t a2, uint32_t a3,
                                         uint32_t b0, uint32_t b1,
                                         const float* c) {
    asm("mma.sync.aligned.m16n8k16.row.col.f32.f16.f16.f32 "
        "{%0,%1,%2,%3}, {%4,%5,%6,%7}, {%8,%9}, {%10,%11,%12,%13};"
        : "=f"(d[0]), "=f"(d[1]), "=f"(d[2]), "=f"(d[3])
        : "r"(a0), "r"(a1), "r"(a2), "r"(a3), "r"(b0), "r"(b1),
          "f"(c[0]), "f"(c[1]), "f"(c[2]), "f"(c[3]));
}

__global__ __launch_bounds__(128, 1)
void gru_mma(const float* __restrict__ x,
             const float* __restrict__ w_ih_f, const float* __restrict__ w_hh_f,
             const float* __restrict__ b_ih_f, const float* __restrict__ b_hh_f,
             const float* __restrict__ w_ih_b, const float* __restrict__ w_hh_b,
             const float* __restrict__ b_ih_b, const float* __restrict__ b_hh_b,
             const float* __restrict__ fc_w, const float* __restrict__ fc_b,
             float* __restrict__ out)
{
    const int lane = threadIdx.x & 31;
    const int g    = lane >> 2;          // 0..7
    const int tg   = lane & 3;           // 0..3
    const int gw   = blockIdx.x * 4 + (threadIdx.x >> 5);   // 0..511
    const int dir  = gw >> 8;
    const int wb   = (gw & 255) * 16;

    const float* w_ih = dir ? w_ih_b : w_ih_f;
    const float* w_hh = dir ? w_hh_b : w_hh_f;
    const float* b_ih = dir ? b_ih_b : b_ih_f;
    const float* b_hh = dir ? b_hh_b : b_hh_f;

    // ---- B fragments: W_hh for N-tiles 0..11 (r 0-3, z 4-7, hn 8-11) ----
    uint32_t Bh[12][2][2];
#pragma unroll
    for (int nt = 0; nt < 12; nt++) {
        const int G = nt >> 2;
        const int hcol = (nt & 3) * 8 + g;
        const int grow = G * 32 + hcol;
#pragma unroll
        for (int kp = 0; kp < 2; kp++) {
            const int kb = kp * 16;
            Bh[nt][kp][0] = h2pack(w_hh[grow * 32 + kb + 2 * tg],
                                   w_hh[grow * 32 + kb + 2 * tg + 1]);
            Bh[nt][kp][1] = h2pack(w_hh[grow * 32 + kb + 2 * tg + 8],
                                   w_hh[grow * 32 + kb + 2 * tg + 9]);
        }
    }
    // x-tile B fragments for r (0-3), z (4-7), xn (8-11 here == tiles 12-15)
    uint32_t Bx[12];
#pragma unroll
    for (int q = 0; q < 12; q++) {
        const int G = q >> 2;                   // 0=r, 1=z, 2=xn
        const int hcol = (q & 3) * 8 + g;
        float wi0, wi1, wi2, bias;
        if (G == 0) {
            wi0 = w_ih[hcol * 3]; wi1 = w_ih[hcol * 3 + 1]; wi2 = w_ih[hcol * 3 + 2];
            bias = b_ih[hcol] + b_hh[hcol];
        } else if (G == 1) {
            const int r = 32 + hcol;
            wi0 = w_ih[r * 3]; wi1 = w_ih[r * 3 + 1]; wi2 = w_ih[r * 3 + 2];
            bias = b_ih[r] + b_hh[r];
        } else {
            const int r = 64 + hcol;
            wi0 = w_ih[r * 3]; wi1 = w_ih[r * 3 + 1]; wi2 = w_ih[r * 3 + 2];
            bias = b_ih[r];
        }
        Bx[q] = (tg == 0) ? h2pack(wi0, wi1)
              : (tg == 1) ? h2pack(wi2, bias)
              : (tg == 2) ? h2pack(wi0, wi1)
                          : h2pack(wi2, 0.f);
    }
    // hn bias C-init values: cols 2tg, 2tg+1 of each hn tile
    float bn0[4], bn1[4];
#pragma unroll
    for (int q = 0; q < 4; q++) {
        bn0[q] = b_hh[64 + q * 8 + 2 * tg];
        bn1[q] = b_hh[64 + q * 8 + 2 * tg + 1];
    }

    float fw[4][2];
#pragma unroll
    for (int j = 0; j < 4; j++) {
        fw[j][0] = fc_w[dir * HH + 8 * j + 2 * tg];
        fw[j][1] = fc_w[dir * HH + 8 * j + 2 * tg + 1];
    }
    const float fcb = fc_b[0];

    float hh[4][4];
#pragma unroll
    for (int j = 0; j < 4; j++)
#pragma unroll
        for (int p = 0; p < 4; p++) hh[j][p] = 0.f;
    uint32_t Ah[2][4], Al[2][4];
#pragma unroll
    for (int kt = 0; kt < 2; kt++)
#pragma unroll
        for (int q = 0; q < 4; q++) { Ah[kt][q] = 0u; Al[kt][q] = 0u; }

    const int tf = dir ? (TT - 1) : 0;
    float xa0, xa1, xa2, xb0, xb1, xb2;
    {
        const float* p0 = x + ((size_t)tf * BN + wb + g) * 3;
        const float* p1 = x + ((size_t)tf * BN + wb + g + 8) * 3;
        xa0 = p0[0]; xa1 = p0[1]; xa2 = p0[2];
        xb0 = p1[0]; xb1 = p1[1]; xb2 = p1[2];
    }

    const float zc[4] = {0.f, 0.f, 0.f, 0.f};

#pragma unroll 1
    for (int s = 0; s < TT; s++) {
        const int t = dir ? (TT - 1 - s) : s;

        // ---- A x-tile fragment (hi + residual lo) ----
        uint32_t ax0, ax1;
        {
            float la0, la1, la2, lb0, lb1, lb2;
            {
                float2 u;
                u = h2unpack(h2pack(xa0, xa1)); la0 = xa0 - u.x; la1 = xa1 - u.y;
                u = h2unpack(h2pack(xa2, xb0)); la2 = xa2 - u.x; lb0 = xb0 - u.y;
                u = h2unpack(h2pack(xb1, xb2)); lb1 = xb1 - u.x; lb2 = xb2 - u.y;
            }
            ax0 = (tg == 0) ? h2pack(xa0, xa1)
                : (tg == 1) ? h2pack(xa2, 1.f)
                : (tg == 2) ? h2pack(la0, la1)
                            : h2pack(la2, 0.f);
            ax1 = (tg == 0) ? h2pack(xb0, xb1)
                : (tg == 1) ? h2pack(xb2, 1.f)
                : (tg == 2) ? h2pack(lb0, lb1)
                            : h2pack(lb2, 0.f);
        }

        // ---- MMA chain: D[16][4] ----
        // tiles 0-3 r, 4-7 z, 8-11 hn, 12-15 xn
        float D[16][4];
        // x-pass: r, z, xn (12 MMAs)
#pragma unroll
        for (int q = 0; q < 8; q++)
            mma16816(D[q], ax0, ax1, 0u, 0u, Bx[q], 0u, zc);
#pragma unroll
        for (int q = 0; q < 4; q++)
            mma16816(D[12 + q], ax0, ax1, 0u, 0u, Bx[8 + q], 0u, zc);
        // hn: C-init with bias, then hi + lo passes (16 MMAs)
#pragma unroll
        for (int q = 0; q < 4; q++) {
            const float bc[4] = {bn0[q], bn1[q], bn0[q], bn1[q]};
            mma16816(D[8 + q], Ah[0][0], Ah[0][1], Ah[0][2], Ah[0][3], Bh[8 + q][0][0], Bh[8 + q][0][1], bc);
            mma16816(D[8 + q], Ah[1][0], Ah[1][1], Ah[1][2], Ah[1][3], Bh[8 + q][1][0], Bh[8 + q][1][1], D[8 + q]);
            mma16816(D[8 + q], Al[0][0], Al[0][1], Al[0][2], Al[0][3], Bh[8 + q][0][0], Bh[8 + q][0][1], D[8 + q]);
            mma16816(D[8 + q], Al[1][0], Al[1][1], Al[1][2], Al[1][3], Bh[8 + q][1][0], Bh[8 + q][1][1], D[8 + q]);
        }
        // r, z: hi passes only (16 MMAs)
#pragma unroll
        for (int nt = 0; nt < 8; nt++) {
            mma16816(D[nt], Ah[0][0], Ah[0][1], Ah[0][2], Ah[0][3], Bh[nt][0][0], Bh[nt][0][1], D[nt]);
            mma16816(D[nt], Ah[1][0], Ah[1][1], Ah[1][2], Ah[1][3], Bh[nt][1][0], Bh[nt][1][1], D[nt]);
        }

        // prefetch next x
        const int tn = dir ? (t > 0 ? t - 1 : 0) : (t < TT - 1 ? t + 1 : t);
        {
            const float* p0 = x + ((size_t)tn * BN + wb + g) * 3;
            const float* p1 = x + ((size_t)tn * BN + wb + g + 8) * 3;
            xa0 = p0[0]; xa1 = p0[1]; xa2 = p0[2];
            xb0 = p1[0]; xb1 = p1[1]; xb2 = p1[2];
        }

        // ---- epilogue: gates, h update, FC partials ----
        float v0 = 0.f, v1 = 0.f;
#pragma unroll
        for (int j = 0; j < 4; j++) {
#pragma unroll
            for (int p = 0; p < 4; p++) {
                const float r = sigm(D[j][p]);
                const float z = sigm(D[4 + j][p]);
                const float n = tanh_fast(fmaf(r, D[8 + j][p], D[12 + j][p]));
                const float hv = fmaf(z, hh[j][p] - n, n);
                hh[j][p] = hv;
                const float c = hv * fw[j][p & 1];
                if (p < 2) v0 += c; else v1 += c;
            }
        }

        // ---- rebuild A h fragments (hi) + residual (lo) ----
#pragma unroll
        for (int kt = 0; kt < 2; kt++) {
#pragma unroll
            for (int q = 0; q < 4; q++) {
                const int j = kt * 2 + (q >> 1);
                const int p = (q & 1) * 2;
                const float a = hh[j][p], b = hh[j][p + 1];
                const uint32_t hi = h2pack(a, b);
                Ah[kt][q] = hi;
                const float2 u = h2unpack(hi);
                Al[kt][q] = h2pack(a - u.x, b - u.y);
            }
        }

        // ---- FC reduce over 4-lane group, write ----
        v0 += __shfl_xor_sync(0xffffffffu, v0, 1);
        v0 += __shfl_xor_sync(0xffffffffu, v0, 2);
        v1 += __shfl_xor_sync(0xffffffffu, v1, 1);
        v1 += __shfl_xor_sync(0xffffffffu, v1, 2);
        if (tg == 0) {
            const size_t o0 = (size_t)t * BN + wb + g;
            if (dir == 0) { out[o0] = v0 + fcb; out[o0 + 8] = v1 + fcb; }
            else          { g_scr[o0] = v0;     g_scr[o0 + 8] = v1; }
        }
    }
}

__global__ __launch_bounds__(256)
void combine_add(float* __restrict__ out)
{
    const int i = blockIdx.x * blockDim.x + threadIdx.x;
    float4* o = reinterpret_cast<float4*>(out);
    const float4* s = reinterpret_cast<const float4*>(g_scr);
    float4 a = o[i];
    const float4 c = s[i];
    a.x += c.x; a.y += c.y; a.z += c.z; a.w += c.w;
    o[i] = a;
}

extern "C" void kernel_launch(void* const* d_in, const int* in_sizes, int n_in,
                              void* d_out, int out_size)
{
    (void)in_sizes; (void)n_in; (void)out_size;
    const float* x      = (const float*)d_in[0];
    const float* w_ih_f = (const float*)d_in[1];
    const float* w_hh_f = (const float*)d_in[2];
    const float* b_ih_f = (const float*)d_in[3];
    const float* b_hh_f = (const float*)d_in[4];
    const float* w_ih_b = (const float*)d_in[5];
    const float* w_hh_b = (const float*)d_in[6];
    const float* b_ih_b = (const float*)d_in[7];
    const float* b_hh_b = (const float*)d_in[8];
    const float* fc_w   = (const float*)d_in[9];
    const float* fc_b   = (const float*)d_in[10];
    float* out = (float*)d_out;

    gru_mma<<<128, 128>>>(x, w_ih_f, w_hh_f, b_ih_f, b_hh_f,
                          w_ih_b, w_hh_b, b_ih_b, b_hh_b, fc_w, fc_b, out);
    combine_add<<<(TT * BN / 4) / 256, 256>>>(out);
}

// round 12
// speedup vs baseline: 4.7613x; 1.0011x over previous
#include <cuda_runtime.h>
#include <cuda_fp16.h>
#include <cstdint>
#include <cstddef>

// GRU_13907104105002 — R12: HMMA recurrence, 36 MMAs (12 of them k8).
// R11 evidence: error floor is f16 W_hh rounding (removing r/z h-residual
// didn't move rel_err). R12: (1) drop hn h-residual passes too (-8 MMAs, Al
// gone); (2) x-pass uses m16n8k8 (x-tile occupies exactly K slots 0-7);
// (3) r,z sigmoids via tanh.approx.f16x2 (MUFU 48 -> 32 ops); n tanh stays
// f32. h stays in registers across steps (D-fragment == next A-fragment).
// fwd writes out, bwd writes scratch, float4 combine adds.

#define TT 200
#define BN 4096
#define HH 32

__device__ float g_scr[TT * BN];

__device__ __forceinline__ float tanh_fast(float x) {
    float y; asm("tanh.approx.f32 %0, %1;" : "=f"(y) : "f"(x)); return y;
}
// pack {low=a, high=b} as f16x2
__device__ __forceinline__ uint32_t h2pack(float a, float b) {
    uint32_t d; asm("cvt.rn.f16x2.f32 %0, %1, %2;" : "=r"(d) : "f"(b), "f"(a)); return d;
}
__device__ __forceinline__ float2 h2unpack(uint32_t v) {
    __half2 h = *reinterpret_cast<__half2*>(&v);
    return __half22float2(h);
}
// sigmoid on a packed f16x2 pair: 0.5*tanh(0.5x)+0.5
__device__ __forceinline__ uint32_t sigm2(uint32_t u) {
    const uint32_t H05 = 0x38003800u;
    uint32_t t, d;
    asm("mul.rn.f16x2 %0, %1, %2;" : "=r"(t) : "r"(u), "r"(H05));
    asm("tanh.approx.f16x2 %0, %1;" : "=r"(t) : "r"(t));
    asm("fma.rn.f16x2 %0, %1, %2, %3;" : "=r"(d) : "r"(t), "r"(H05), "r"(H05));
    return d;
}
__device__ __forceinline__ void mma16816(float* d,
                                         uint32_t a0, uint32_t a1, uint32_t a2, uint32_t a3,
                                         uint32_t b0, uint32_t b1,
                                         const float* c) {
    asm("mma.sync.aligned.m16n8k16.row.col.f32.f16.f16.f32 "
        "{%0,%1,%2,%3}, {%4,%5,%6,%7}, {%8,%9}, {%10,%11,%12,%13};"
        : "=f"(d[0]), "=f"(d[1]), "=f"(d[2]), "=f"(d[3])
        : "r"(a0), "r"(a1), "r"(a2), "r"(a3), "r"(b0), "r"(b1),
          "f"(c[0]), "f"(c[1]), "f"(c[2]), "f"(c[3]));
}
__device__ __forceinline__ void mma1688(float* d,
                                        uint32_t a0, uint32_t a1, uint32_t b0,
                                        const float* c) {
    asm("mma.sync.aligned.m16n8k8.row.col.f32.f16.f16.f32 "
        "{%0,%1,%2,%3}, {%4,%5}, {%6}, {%7,%8,%9,%10};"
        : "=f"(d[0]), "=f"(d[1]), "=f"(d[2]), "=f"(d[3])
        : "r"(a0), "r"(a1), "r"(b0),
          "f"(c[0]), "f"(c[1]), "f"(c[2]), "f"(c[3]));
}

__global__ __launch_bounds__(128, 1)
void gru_mma(const float* __restrict__ x,
             const float* __restrict__ w_ih_f, const float* __restrict__ w_hh_f,
             const float* __restrict__ b_ih_f, const float* __restrict__ b_hh_f,
             const float* __restrict__ w_ih_b, const float* __restrict__ w_hh_b,
             const float* __restrict__ b_ih_b, const float* __restrict__ b_hh_b,
             const float* __restrict__ fc_w, const float* __restrict__ fc_b,
             float* __restrict__ out)
{
    const int lane = threadIdx.x & 31;
    const int g    = lane >> 2;          // 0..7
    const int tg   = lane & 3;           // 0..3
    const int gw   = blockIdx.x * 4 + (threadIdx.x >> 5);   // 0..511
    const int dir  = gw >> 8;
    const int wb   = (gw & 255) * 16;

    const float* w_ih = dir ? w_ih_b : w_ih_f;
    const float* w_hh = dir ? w_hh_b : w_hh_f;
    const float* b_ih = dir ? b_ih_b : b_ih_f;
    const float* b_hh = dir ? b_hh_b : b_hh_f;

    // ---- W_hh B fragments for N-tiles 0..11 (r 0-3, z 4-7, hn 8-11) ----
    uint32_t Bh[12][2][2];
#pragma unroll
    for (int nt = 0; nt < 12; nt++) {
        const int G = nt >> 2;
        const int hcol = (nt & 3) * 8 + g;
        const int grow = G * 32 + hcol;
#pragma unroll
        for (int kp = 0; kp < 2; kp++) {
            const int kb = kp * 16;
            Bh[nt][kp][0] = h2pack(w_hh[grow * 32 + kb + 2 * tg],
                                   w_hh[grow * 32 + kb + 2 * tg + 1]);
            Bh[nt][kp][1] = h2pack(w_hh[grow * 32 + kb + 2 * tg + 8],
                                   w_hh[grow * 32 + kb + 2 * tg + 9]);
        }
    }
    // x-tile B fragments (K=8): r (0-3), z (4-7), xn (8-11)
    uint32_t Bx[12];
#pragma unroll
    for (int q = 0; q < 12; q++) {
        const int G = q >> 2;                   // 0=r, 1=z, 2=xn
        const int hcol = (q & 3) * 8 + g;
        float wi0, wi1, wi2, bias;
        if (G == 0) {
            wi0 = w_ih[hcol * 3]; wi1 = w_ih[hcol * 3 + 1]; wi2 = w_ih[hcol * 3 + 2];
            bias = b_ih[hcol] + b_hh[hcol];
        } else if (G == 1) {
            const int r = 32 + hcol;
            wi0 = w_ih[r * 3]; wi1 = w_ih[r * 3 + 1]; wi2 = w_ih[r * 3 + 2];
            bias = b_ih[r] + b_hh[r];
        } else {
            const int r = 64 + hcol;
            wi0 = w_ih[r * 3]; wi1 = w_ih[r * 3 + 1]; wi2 = w_ih[r * 3 + 2];
            bias = b_ih[r];
        }
        Bx[q] = (tg == 0) ? h2pack(wi0, wi1)
              : (tg == 1) ? h2pack(wi2, bias)
              : (tg == 2) ? h2pack(wi0, wi1)
                          : h2pack(wi2, 0.f);
    }
    // hn bias C-init values
    float bn0[4], bn1[4];
#pragma unroll
    for (int q = 0; q < 4; q++) {
        bn0[q] = b_hh[64 + q * 8 + 2 * tg];
        bn1[q] = b_hh[64 + q * 8 + 2 * tg + 1];
    }

    float fw[4][2];
#pragma unroll
    for (int j = 0; j < 4; j++) {
        fw[j][0] = fc_w[dir * HH + 8 * j + 2 * tg];
        fw[j][1] = fc_w[dir * HH + 8 * j + 2 * tg + 1];
    }
    const float fcb = fc_b[0];

    float hh[4][4];
#pragma unroll
    for (int j = 0; j < 4; j++)
#pragma unroll
        for (int p = 0; p < 4; p++) hh[j][p] = 0.f;
    uint32_t Ah[2][4];
#pragma unroll
    for (int kt = 0; kt < 2; kt++)
#pragma unroll
        for (int q = 0; q < 4; q++) Ah[kt][q] = 0u;

    const int tf = dir ? (TT - 1) : 0;
    float xa0, xa1, xa2, xb0, xb1, xb2;
    {
        const float* p0 = x + ((size_t)tf * BN + wb + g) * 3;
        const float* p1 = x + ((size_t)tf * BN + wb + g + 8) * 3;
        xa0 = p0[0]; xa1 = p0[1]; xa2 = p0[2];
        xb0 = p1[0]; xb1 = p1[1]; xb2 = p1[2];
    }

    const float zc[4] = {0.f, 0.f, 0.f, 0.f};

#pragma unroll 1
    for (int s = 0; s < TT; s++) {
        const int t = dir ? (TT - 1 - s) : s;

        // ---- A x-tile fragment (hi + residual lo, K slots 0-7) ----
        uint32_t ax0, ax1;
        {
            float la0, la1, la2, lb0, lb1, lb2;
            {
                float2 u;
                u = h2unpack(h2pack(xa0, xa1)); la0 = xa0 - u.x; la1 = xa1 - u.y;
                u = h2unpack(h2pack(xa2, xb0)); la2 = xa2 - u.x; lb0 = xb0 - u.y;
                u = h2unpack(h2pack(xb1, xb2)); lb1 = xb1 - u.x; lb2 = xb2 - u.y;
            }
            ax0 = (tg == 0) ? h2pack(xa0, xa1)
                : (tg == 1) ? h2pack(xa2, 1.f)
                : (tg == 2) ? h2pack(la0, la1)
                            : h2pack(la2, 0.f);
            ax1 = (tg == 0) ? h2pack(xb0, xb1)
                : (tg == 1) ? h2pack(xb2, 1.f)
                : (tg == 2) ? h2pack(lb0, lb1)
                            : h2pack(lb2, 0.f);
        }

        // ---- MMA chain: D[16][4]; tiles 0-3 r, 4-7 z, 8-11 hn, 12-15 xn ----
        float D[16][4];
        // x-pass (K=8): r, z (8), xn (4)
#pragma unroll
        for (int q = 0; q < 8; q++)
            mma1688(D[q], ax0, ax1, Bx[q], zc);
#pragma unroll
        for (int q = 0; q < 4; q++)
            mma1688(D[12 + q], ax0, ax1, Bx[8 + q], zc);
        // hn: C-init bias + 2 hi passes (8)
#pragma unroll
        for (int q = 0; q < 4; q++) {
            const float bc[4] = {bn0[q], bn1[q], bn0[q], bn1[q]};
            mma16816(D[8 + q], Ah[0][0], Ah[0][1], Ah[0][2], Ah[0][3], Bh[8 + q][0][0], Bh[8 + q][0][1], bc);
            mma16816(D[8 + q], Ah[1][0], Ah[1][1], Ah[1][2], Ah[1][3], Bh[8 + q][1][0], Bh[8 + q][1][1], D[8 + q]);
        }
        // r, z: 2 hi passes each (16)
#pragma unroll
        for (int nt = 0; nt < 8; nt++) {
            mma16816(D[nt], Ah[0][0], Ah[0][1], Ah[0][2], Ah[0][3], Bh[nt][0][0], Bh[nt][0][1], D[nt]);
            mma16816(D[nt], Ah[1][0], Ah[1][1], Ah[1][2], Ah[1][3], Bh[nt][1][0], Bh[nt][1][1], D[nt]);
        }

        // prefetch next x
        const int tn = dir ? (t > 0 ? t - 1 : 0) : (t < TT - 1 ? t + 1 : t);
        {
            const float* p0 = x + ((size_t)tn * BN + wb + g) * 3;
            const float* p1 = x + ((size_t)tn * BN + wb + g + 8) * 3;
            xa0 = p0[0]; xa1 = p0[1]; xa2 = p0[2];
            xb0 = p1[0]; xb1 = p1[1]; xb2 = p1[2];
        }

        // ---- epilogue: r,z via f16x2 tanh; n via f32 tanh; h update; FC ----
        float v0 = 0.f, v1 = 0.f;
#pragma unroll
        for (int j = 0; j < 4; j++) {
            const float2 r01 = h2unpack(sigm2(h2pack(D[j][0], D[j][1])));
            const float2 r23 = h2unpack(sigm2(h2pack(D[j][2], D[j][3])));
            const float2 z01 = h2unpack(sigm2(h2pack(D[4 + j][0], D[4 + j][1])));
            const float2 z23 = h2unpack(sigm2(h2pack(D[4 + j][2], D[4 + j][3])));
            const float rr[4] = {r01.x, r01.y, r23.x, r23.y};
            const float zz[4] = {z01.x, z01.y, z23.x, z23.y};
#pragma unroll
            for (int p = 0; p < 4; p++) {
                const float n = tanh_fast(fmaf(rr[p], D[8 + j][p], D[12 + j][p]));
                const float hv = fmaf(zz[p], hh[j][p] - n, n);
                hh[j][p] = hv;
                const float c = hv * fw[j][p & 1];
                if (p < 2) v0 += c; else v1 += c;
            }
        }

        // ---- rebuild A h fragments (hi only) ----
#pragma unroll
        for (int kt = 0; kt < 2; kt++) {
#pragma unroll
            for (int q = 0; q < 4; q++) {
                const int j = kt * 2 + (q >> 1);
                const int p = (q & 1) * 2;
                Ah[kt][q] = h2pack(hh[j][p], hh[j][p + 1]);
            }
        }

        // ---- FC reduce over 4-lane group, write ----
        v0 += __shfl_xor_sync(0xffffffffu, v0, 1);
        v0 += __shfl_xor_sync(0xffffffffu, v0, 2);
        v1 += __shfl_xor_sync(0xffffffffu, v1, 1);
        v1 += __shfl_xor_sync(0xffffffffu, v1, 2);
        if (tg == 0) {
            const size_t o0 = (size_t)t * BN + wb + g;
            if (dir == 0) { out[o0] = v0 + fcb; out[o0 + 8] = v1 + fcb; }
            else          { g_scr[o0] = v0;     g_scr[o0 + 8] = v1; }
        }
    }
}

__global__ __launch_bounds__(256)
void combine_add(float* __restrict__ out)
{
    const int i = blockIdx.x * blockDim.x + threadIdx.x;
    float4* o = reinterpret_cast<float4*>(out);
    const float4* s = reinterpret_cast<const float4*>(g_scr);
    float4 a = o[i];
    const float4 c = s[i];
    a.x += c.x; a.y += c.y; a.z += c.z; a.w += c.w;
    o[i] = a;
}

extern "C" void kernel_launch(void* const* d_in, const int* in_sizes, int n_in,
                              void* d_out, int out_size)
{
    (void)in_sizes; (void)n_in; (void)out_size;
    const float* x      = (const float*)d_in[0];
    const float* w_ih_f = (const float*)d_in[1];
    const float* w_hh_f = (const float*)d_in[2];
    const float* b_ih_f = (const float*)d_in[3];
    const float* b_hh_f = (const float*)d_in[4];
    const float* w_ih_b = (const float*)d_in[5];
    const float* w_hh_b = (const float*)d_in[6];
    const float* b_ih_b = (const float*)d_in[7];
    const float* b_hh_b = (const float*)d_in[8];
    const float* fc_w   = (const float*)d_in[9];
    const float* fc_b   = (const float*)d_in[10];
    float* out = (float*)d_out;

    gru_mma<<<128, 128>>>(x, w_ih_f, w_hh_f, b_ih_f, b_hh_f,
                          w_ih_b, w_hh_b, b_ih_b, b_hh_b, fc_w, fc_b, out);
    combine_add<<<(TT * BN / 4) / 256, 256>>>(out);
}